// round 12
// baseline (speedup 1.0000x reference)
#include <cuda_runtime.h>
#include <cuda_fp16.h>
#include <cstdint>

// LightGCN propagation on GB300 — round 12.
// out = (h0 + A h0 + A^2 h0 + A^3 h0)/4, A = D^-1/2 Adj D^-1/2 (COO), D=64.
//
// vs R11 (gather AND permute both measured at their hardware floors):
//  k_zero eliminated via replay-invariant state:
//   - s-buffer sentinel rows: __device__ globals are zero-initialized at module
//     load and never written by any kernel -> no runtime zeroing needed.
//   - g_cnt: k_final self-cleans (reads cnt, then lane (i&7)==0 stores 0 for
//     the next launch; read precedes write in warp program order, groups of 8
//     never straddle a warp). Inductive invariant across graph replays.

#define DIM    64
#define NMAX   150002
#define PAD    128          // slots per node
#define PSHIFT 7

// prescaled layer buffers s0..s3, fp16 rows of 128B (8 uint4 per row)
// +1 row per buffer: the zero sentinel at row N (zero-init at load, never written)
__device__ uint4 g_s[4][(size_t)(NMAX + 1) * 8];
__device__ int   g_cnt[NMAX];     // zero at launch start (load-init + k_final self-clean)
__device__ int   g_pcol[(size_t)NMAX * PAD];

// --- permute into padded slots: 4 symmetric edge-pairs per thread ---------------
__global__ void k_permute(const int4* __restrict__ rows4,
                          const int4* __restrict__ cols4, int E4,
                          const int* __restrict__ rows,
                          const int* __restrict__ cols, int E) {
    int i = blockIdx.x * blockDim.x + threadIdx.x;
    if (i < E4) {
        int4 r = __ldg(rows4 + i);
        int4 c = __ldg(cols4 + i);
        int p;
        p = atomicAdd(&g_cnt[r.x], 1); g_pcol[(r.x << PSHIFT) + p] = c.x;
        p = atomicAdd(&g_cnt[c.x], 1); g_pcol[(c.x << PSHIFT) + p] = r.x;
        p = atomicAdd(&g_cnt[r.y], 1); g_pcol[(r.y << PSHIFT) + p] = c.y;
        p = atomicAdd(&g_cnt[c.y], 1); g_pcol[(c.y << PSHIFT) + p] = r.y;
        p = atomicAdd(&g_cnt[r.z], 1); g_pcol[(r.z << PSHIFT) + p] = c.z;
        p = atomicAdd(&g_cnt[c.z], 1); g_pcol[(c.z << PSHIFT) + p] = r.z;
        p = atomicAdd(&g_cnt[r.w], 1); g_pcol[(r.w << PSHIFT) + p] = c.w;
        p = atomicAdd(&g_cnt[c.w], 1); g_pcol[(c.w << PSHIFT) + p] = r.w;
    }
    int t = E4 * 4 + i;
    if (i < E - E4 * 4) {
        int r = __ldg(rows + t), c = __ldg(cols + t);
        int p;
        p = atomicAdd(&g_cnt[r], 1); g_pcol[(r << PSHIFT) + p] = c;
        p = atomicAdd(&g_cnt[c], 1); g_pcol[(c << PSHIFT) + p] = r;
    }
}

// --- fused init + sentinel pad (both depend only on permute; overlap on SMs) ----
// blocks [0, initBlocks): s0 = half2(dinv .* h0), 16B per thread
// blocks [initBlocks, ..): fill bucket slots [deg, roundup32(deg)) with N
__global__ void k_init_pad(const float4* __restrict__ user,
                           const float4* __restrict__ item,
                           int u4, int n8, int n, int initBlocks) {
    if ((int)blockIdx.x < initBlocks) {
        int i = blockIdx.x * blockDim.x + threadIdx.x;   // uint4 index
        if (i >= n8) return;
        int f4 = i * 2;
        float4 va, vb;
        if (f4 < u4) { va = __ldg(user + f4); vb = __ldg(user + f4 + 1); }
        else         { va = __ldg(item + (f4 - u4)); vb = __ldg(item + (f4 - u4) + 1); }
        float di = rsqrtf((float)__ldg(&g_cnt[i >> 3]) + 1e-7f);
        __half2 h0 = __floats2half2_rn(di * va.x, di * va.y);
        __half2 h1 = __floats2half2_rn(di * va.z, di * va.w);
        __half2 h2 = __floats2half2_rn(di * vb.x, di * vb.y);
        __half2 h3 = __floats2half2_rn(di * vb.z, di * vb.w);
        uint4 o;
        o.x = *(const unsigned*)&h0; o.y = *(const unsigned*)&h1;
        o.z = *(const unsigned*)&h2; o.w = *(const unsigned*)&h3;
        g_s[0][i] = o;
    } else {
        int j = ((int)blockIdx.x - initBlocks) * blockDim.x + threadIdx.x;
        if (j >= n * 32) return;
        int node = j >> 5;
        int k    = j & 31;
        int deg  = __ldg(&g_cnt[node]);
        int slot = (deg & ~31) + k;     // last (partial) chunk of the bucket
        if (slot >= deg && slot < PAD)
            g_pcol[(node << PSHIFT) + slot] = n;   // sentinel: zero row
    }
}

// --- gather SpMM: warp/row; unconditional batched MLP-8 chunks; HADD2 ----------
__global__ void k_gather(const uint4* __restrict__ x,
                         uint4* __restrict__ y, int n) {
    int gw   = (blockIdx.x * blockDim.x + threadIdx.x) >> 5;
    int lane = threadIdx.x & 31;
    if (gw >= n) return;
    int s   = gw << PSHIFT;
    int deg = __ldg(&g_cnt[gw]);
    int e   = s + deg;
    int h = lane >> 3;          // edge-of-4 subgroup (0..3)
    int q = lane & 7;           // 16B slice of the 128B row

    // hoist the MUFU ops: overlap with the load loop
    float di  = rsqrtf((float)deg + 1e-7f);
    float di2 = di * di;        // s_next = dinv^2 * sum

    float a0 = 0.f, a1 = 0.f, a2 = 0.f, a3 = 0.f;
    float a4 = 0.f, a5 = 0.f, a6 = 0.f, a7 = 0.f;

    int c = __ldg(&g_pcol[s + lane]);           // always in-bounds

    for (int base = s; base < e; base += 32) {
        int c_cur = c;
        if (base + 32 < e)                       // prefetch next chunk's indices
            c = __ldg(&g_pcol[base + 32 + lane]);

        // 8 uniform group indices (slots past deg hold the zero sentinel)
        int cj0 = __shfl_sync(0xffffffffu, c_cur,  0 + h);
        int cj1 = __shfl_sync(0xffffffffu, c_cur,  4 + h);
        int cj2 = __shfl_sync(0xffffffffu, c_cur,  8 + h);
        int cj3 = __shfl_sync(0xffffffffu, c_cur, 12 + h);
        int cj4 = __shfl_sync(0xffffffffu, c_cur, 16 + h);
        int cj5 = __shfl_sync(0xffffffffu, c_cur, 20 + h);
        int cj6 = __shfl_sync(0xffffffffu, c_cur, 24 + h);
        int cj7 = __shfl_sync(0xffffffffu, c_cur, 28 + h);

        // 8 unconditional back-to-back LDG.128 (MLP 8)
        uint4 r0 = __ldg(x + cj0 * 8 + q);
        uint4 r1 = __ldg(x + cj1 * 8 + q);
        uint4 r2 = __ldg(x + cj2 * 8 + q);
        uint4 r3 = __ldg(x + cj3 * 8 + q);
        uint4 r4 = __ldg(x + cj4 * 8 + q);
        uint4 r5 = __ldg(x + cj5 * 8 + q);
        uint4 r6 = __ldg(x + cj6 * 8 + q);
        uint4 r7 = __ldg(x + cj7 * 8 + q);

        // fp16 chunk accumulation (sentinel zeros are exact)
        __half2 zz = __floats2half2_rn(0.f, 0.f);
        __half2 c0 = zz, c1 = zz, c2 = zz, c3 = zz;
        c0 = __hadd2(c0, *(const __half2*)&r0.x);
        c1 = __hadd2(c1, *(const __half2*)&r0.y);
        c2 = __hadd2(c2, *(const __half2*)&r0.z);
        c3 = __hadd2(c3, *(const __half2*)&r0.w);
        c0 = __hadd2(c0, *(const __half2*)&r1.x);
        c1 = __hadd2(c1, *(const __half2*)&r1.y);
        c2 = __hadd2(c2, *(const __half2*)&r1.z);
        c3 = __hadd2(c3, *(const __half2*)&r1.w);
        c0 = __hadd2(c0, *(const __half2*)&r2.x);
        c1 = __hadd2(c1, *(const __half2*)&r2.y);
        c2 = __hadd2(c2, *(const __half2*)&r2.z);
        c3 = __hadd2(c3, *(const __half2*)&r2.w);
        c0 = __hadd2(c0, *(const __half2*)&r3.x);
        c1 = __hadd2(c1, *(const __half2*)&r3.y);
        c2 = __hadd2(c2, *(const __half2*)&r3.z);
        c3 = __hadd2(c3, *(const __half2*)&r3.w);
        c0 = __hadd2(c0, *(const __half2*)&r4.x);
        c1 = __hadd2(c1, *(const __half2*)&r4.y);
        c2 = __hadd2(c2, *(const __half2*)&r4.z);
        c3 = __hadd2(c3, *(const __half2*)&r4.w);
        c0 = __hadd2(c0, *(const __half2*)&r5.x);
        c1 = __hadd2(c1, *(const __half2*)&r5.y);
        c2 = __hadd2(c2, *(const __half2*)&r5.z);
        c3 = __hadd2(c3, *(const __half2*)&r5.w);
        c0 = __hadd2(c0, *(const __half2*)&r6.x);
        c1 = __hadd2(c1, *(const __half2*)&r6.y);
        c2 = __hadd2(c2, *(const __half2*)&r6.z);
        c3 = __hadd2(c3, *(const __half2*)&r6.w);
        c0 = __hadd2(c0, *(const __half2*)&r7.x);
        c1 = __hadd2(c1, *(const __half2*)&r7.y);
        c2 = __hadd2(c2, *(const __half2*)&r7.z);
        c3 = __hadd2(c3, *(const __half2*)&r7.w);

        float2 f;
        f = __half22float2(c0); a0 += f.x; a1 += f.y;
        f = __half22float2(c1); a2 += f.x; a3 += f.y;
        f = __half22float2(c2); a4 += f.x; a5 += f.y;
        f = __half22float2(c3); a6 += f.x; a7 += f.y;
    }

    // reduce across the 4 edge subgroups (q preserved by xor 8/16)
    #pragma unroll
    for (int d = 8; d <= 16; d <<= 1) {
        a0 += __shfl_xor_sync(0xffffffffu, a0, d);
        a1 += __shfl_xor_sync(0xffffffffu, a1, d);
        a2 += __shfl_xor_sync(0xffffffffu, a2, d);
        a3 += __shfl_xor_sync(0xffffffffu, a3, d);
        a4 += __shfl_xor_sync(0xffffffffu, a4, d);
        a5 += __shfl_xor_sync(0xffffffffu, a5, d);
        a6 += __shfl_xor_sync(0xffffffffu, a6, d);
        a7 += __shfl_xor_sync(0xffffffffu, a7, d);
    }

    if (h == 0) {
        __half2 o0 = __floats2half2_rn(di2 * a0, di2 * a1);
        __half2 o1 = __floats2half2_rn(di2 * a2, di2 * a3);
        __half2 o2 = __floats2half2_rn(di2 * a4, di2 * a5);
        __half2 o3 = __floats2half2_rn(di2 * a6, di2 * a7);
        uint4 o;
        o.x = *(const unsigned*)&o0; o.y = *(const unsigned*)&o1;
        o.z = *(const unsigned*)&o2; o.w = *(const unsigned*)&o3;
        y[gw * 8 + q] = o;
    }
}

// --- final: out = 0.25*(h0 + rdinv*(s1+s2+s3)); self-cleans g_cnt --------------
__global__ void k_final(const float4* __restrict__ user,
                        const float4* __restrict__ item,
                        float4* __restrict__ out, int u4, int n8) {
    int i = blockIdx.x * blockDim.x + threadIdx.x;   // uint4 index
    if (i >= n8) return;
    int f4 = i * 2;
    float4 va, vb;
    if (f4 < u4) { va = __ldg(user + f4); vb = __ldg(user + f4 + 1); }
    else         { va = __ldg(item + (f4 - u4)); vb = __ldg(item + (f4 - u4) + 1); }
    uint4 s1 = g_s[1][i], s2 = g_s[2][i], s3 = g_s[3][i];

    // read count, THEN lane (i&7)==0 zeroes it for the next graph replay.
    // 8-thread groups never straddle a warp; read precedes write in program order.
    int node = i >> 3;
    int cnt  = g_cnt[node];
    if ((i & 7) == 0) g_cnt[node] = 0;
    float rd = sqrtf((float)cnt + 1e-7f);

    float acc[8];
    #pragma unroll
    for (int k = 0; k < 4; k++) {
        float2 f1 = __half22float2(*((const __half2*)&s1 + k));
        float2 f2 = __half22float2(*((const __half2*)&s2 + k));
        float2 f3 = __half22float2(*((const __half2*)&s3 + k));
        acc[2 * k]     = f1.x + f2.x + f3.x;
        acc[2 * k + 1] = f1.y + f2.y + f3.y;
    }
    float4 oa, ob;
    oa.x = 0.25f * (va.x + rd * acc[0]);
    oa.y = 0.25f * (va.y + rd * acc[1]);
    oa.z = 0.25f * (va.z + rd * acc[2]);
    oa.w = 0.25f * (va.w + rd * acc[3]);
    ob.x = 0.25f * (vb.x + rd * acc[4]);
    ob.y = 0.25f * (vb.y + rd * acc[5]);
    ob.z = 0.25f * (vb.z + rd * acc[6]);
    ob.w = 0.25f * (vb.w + rd * acc[7]);
    out[f4]     = oa;
    out[f4 + 1] = ob;
}

extern "C" void kernel_launch(void* const* d_in, const int* in_sizes, int n_in,
                              void* d_out, int out_size) {
    const float* user = (const float*)d_in[0];
    const float* item = (const float*)d_in[1];
    const int*   rows = (const int*)  d_in[2];
    const int*   cols = (const int*)  d_in[3];
    // d_in[4] (vals) unused: reconstructed from degrees.
    float* out = (float*)d_out;

    const int U = in_sizes[0] / DIM;
    const int I = in_sizes[1] / DIM;
    const int N = U + I;
    const int NNZ = in_sizes[2];
    const int E = NNZ / 2;          // symmetric COO
    const int E4 = E / 4;

    const int n8 = N * 8;
    const int u4 = U * 16;

    void* ps;
    cudaGetSymbolAddress(&ps, g_s);
    uint4* S0 = (uint4*)ps;
    uint4* S1 = S0 + (size_t)(NMAX + 1) * 8;
    uint4* S2 = S1 + (size_t)(NMAX + 1) * 8;
    uint4* S3 = S2 + (size_t)(NMAX + 1) * 8;

    const int TB  = 256;
    const int TBG = 128;            // gather blocks
    const int gridN8  = (n8 + TB - 1) / TB;
    const int gridE4  = (E4 + TB - 1) / TB;
    const int gridW   = (N * 32 + TBG - 1) / TBG;
    const int gridPad = (N * 32 + TB - 1) / TB;

    k_permute<<<gridE4, TB>>>((const int4*)rows, (const int4*)cols, E4,
                              rows, cols, E);
    k_init_pad<<<gridN8 + gridPad, TB>>>((const float4*)user, (const float4*)item,
                                         u4, n8, N, gridN8);

    k_gather<<<gridW, TBG>>>(S0, S1, N);
    k_gather<<<gridW, TBG>>>(S1, S2, N);
    k_gather<<<gridW, TBG>>>(S2, S3, N);

    k_final<<<gridN8, TB>>>((const float4*)user, (const float4*)item,
                            (float4*)out, u4, n8);
}

// round 13
// speedup vs baseline: 1.0050x; 1.0050x over previous
#include <cuda_runtime.h>
#include <cuda_fp16.h>
#include <cstdint>

// LightGCN propagation on GB300 — round 13.
// out = (h0 + A h0 + A^2 h0 + A^3 h0)/4, A = D^-1/2 Adj D^-1/2 (COO), D=64.
//
// Controlled split of R12's two changes:
//  KEPT:    k_zero elimination (load-time zero-init sentinels + k_final
//           self-cleaning g_cnt) — sound, saves a launch + ~5us.
//  REVERTED: the rsqrt hoist inside k_gather. R12 showed it cost ~3.5us/gather
//           (extended fp32 live ranges across the 8-deep load batch). Gather
//           body below is byte-identical to R11's measured-74.9us version.

#define DIM    64
#define NMAX   150002
#define PAD    128          // slots per node
#define PSHIFT 7

// prescaled layer buffers s0..s3, fp16 rows of 128B (8 uint4 per row)
// +1 row per buffer: the zero sentinel at row N (zero-init at load, never written)
__device__ uint4 g_s[4][(size_t)(NMAX + 1) * 8];
__device__ int   g_cnt[NMAX];     // zero at launch start (load-init + k_final self-clean)
__device__ int   g_pcol[(size_t)NMAX * PAD];

// --- permute into padded slots: 4 symmetric edge-pairs per thread ---------------
__global__ void k_permute(const int4* __restrict__ rows4,
                          const int4* __restrict__ cols4, int E4,
                          const int* __restrict__ rows,
                          const int* __restrict__ cols, int E) {
    int i = blockIdx.x * blockDim.x + threadIdx.x;
    if (i < E4) {
        int4 r = __ldg(rows4 + i);
        int4 c = __ldg(cols4 + i);
        int p;
        p = atomicAdd(&g_cnt[r.x], 1); g_pcol[(r.x << PSHIFT) + p] = c.x;
        p = atomicAdd(&g_cnt[c.x], 1); g_pcol[(c.x << PSHIFT) + p] = r.x;
        p = atomicAdd(&g_cnt[r.y], 1); g_pcol[(r.y << PSHIFT) + p] = c.y;
        p = atomicAdd(&g_cnt[c.y], 1); g_pcol[(c.y << PSHIFT) + p] = r.y;
        p = atomicAdd(&g_cnt[r.z], 1); g_pcol[(r.z << PSHIFT) + p] = c.z;
        p = atomicAdd(&g_cnt[c.z], 1); g_pcol[(c.z << PSHIFT) + p] = r.z;
        p = atomicAdd(&g_cnt[r.w], 1); g_pcol[(r.w << PSHIFT) + p] = c.w;
        p = atomicAdd(&g_cnt[c.w], 1); g_pcol[(c.w << PSHIFT) + p] = r.w;
    }
    int t = E4 * 4 + i;
    if (i < E - E4 * 4) {
        int r = __ldg(rows + t), c = __ldg(cols + t);
        int p;
        p = atomicAdd(&g_cnt[r], 1); g_pcol[(r << PSHIFT) + p] = c;
        p = atomicAdd(&g_cnt[c], 1); g_pcol[(c << PSHIFT) + p] = r;
    }
}

// --- fused init + sentinel pad (both depend only on permute; overlap on SMs) ----
// blocks [0, initBlocks): s0 = half2(dinv .* h0), 16B per thread
// blocks [initBlocks, ..): fill bucket slots [deg, roundup32(deg)) with N
__global__ void k_init_pad(const float4* __restrict__ user,
                           const float4* __restrict__ item,
                           int u4, int n8, int n, int initBlocks) {
    if ((int)blockIdx.x < initBlocks) {
        int i = blockIdx.x * blockDim.x + threadIdx.x;   // uint4 index
        if (i >= n8) return;
        int f4 = i * 2;
        float4 va, vb;
        if (f4 < u4) { va = __ldg(user + f4); vb = __ldg(user + f4 + 1); }
        else         { va = __ldg(item + (f4 - u4)); vb = __ldg(item + (f4 - u4) + 1); }
        float di = rsqrtf((float)__ldg(&g_cnt[i >> 3]) + 1e-7f);
        __half2 h0 = __floats2half2_rn(di * va.x, di * va.y);
        __half2 h1 = __floats2half2_rn(di * va.z, di * va.w);
        __half2 h2 = __floats2half2_rn(di * vb.x, di * vb.y);
        __half2 h3 = __floats2half2_rn(di * vb.z, di * vb.w);
        uint4 o;
        o.x = *(const unsigned*)&h0; o.y = *(const unsigned*)&h1;
        o.z = *(const unsigned*)&h2; o.w = *(const unsigned*)&h3;
        g_s[0][i] = o;
    } else {
        int j = ((int)blockIdx.x - initBlocks) * blockDim.x + threadIdx.x;
        if (j >= n * 32) return;
        int node = j >> 5;
        int k    = j & 31;
        int deg  = __ldg(&g_cnt[node]);
        int slot = (deg & ~31) + k;     // last (partial) chunk of the bucket
        if (slot >= deg && slot < PAD)
            g_pcol[(node << PSHIFT) + slot] = n;   // sentinel: zero row
    }
}

// --- gather SpMM: warp/row; unconditional batched MLP-8 chunks; HADD2 ----------
// EXACT R11 body (measured 74.9us): rsqrt stays in the h==0 epilogue.
__global__ void k_gather(const uint4* __restrict__ x,
                         uint4* __restrict__ y, int n) {
    int gw   = (blockIdx.x * blockDim.x + threadIdx.x) >> 5;
    int lane = threadIdx.x & 31;
    if (gw >= n) return;
    int s   = gw << PSHIFT;
    int deg = __ldg(&g_cnt[gw]);
    int e   = s + deg;
    int h = lane >> 3;          // edge-of-4 subgroup (0..3)
    int q = lane & 7;           // 16B slice of the 128B row

    float a0 = 0.f, a1 = 0.f, a2 = 0.f, a3 = 0.f;
    float a4 = 0.f, a5 = 0.f, a6 = 0.f, a7 = 0.f;

    int c = __ldg(&g_pcol[s + lane]);           // always in-bounds

    for (int base = s; base < e; base += 32) {
        int c_cur = c;
        if (base + 32 < e)                       // prefetch next chunk's indices
            c = __ldg(&g_pcol[base + 32 + lane]);

        // 8 uniform group indices (slots past deg hold the zero sentinel)
        int cj0 = __shfl_sync(0xffffffffu, c_cur,  0 + h);
        int cj1 = __shfl_sync(0xffffffffu, c_cur,  4 + h);
        int cj2 = __shfl_sync(0xffffffffu, c_cur,  8 + h);
        int cj3 = __shfl_sync(0xffffffffu, c_cur, 12 + h);
        int cj4 = __shfl_sync(0xffffffffu, c_cur, 16 + h);
        int cj5 = __shfl_sync(0xffffffffu, c_cur, 20 + h);
        int cj6 = __shfl_sync(0xffffffffu, c_cur, 24 + h);
        int cj7 = __shfl_sync(0xffffffffu, c_cur, 28 + h);

        // 8 unconditional back-to-back LDG.128 (MLP 8)
        uint4 r0 = __ldg(x + cj0 * 8 + q);
        uint4 r1 = __ldg(x + cj1 * 8 + q);
        uint4 r2 = __ldg(x + cj2 * 8 + q);
        uint4 r3 = __ldg(x + cj3 * 8 + q);
        uint4 r4 = __ldg(x + cj4 * 8 + q);
        uint4 r5 = __ldg(x + cj5 * 8 + q);
        uint4 r6 = __ldg(x + cj6 * 8 + q);
        uint4 r7 = __ldg(x + cj7 * 8 + q);

        // fp16 chunk accumulation (sentinel zeros are exact)
        __half2 zz = __floats2half2_rn(0.f, 0.f);
        __half2 c0 = zz, c1 = zz, c2 = zz, c3 = zz;
        c0 = __hadd2(c0, *(const __half2*)&r0.x);
        c1 = __hadd2(c1, *(const __half2*)&r0.y);
        c2 = __hadd2(c2, *(const __half2*)&r0.z);
        c3 = __hadd2(c3, *(const __half2*)&r0.w);
        c0 = __hadd2(c0, *(const __half2*)&r1.x);
        c1 = __hadd2(c1, *(const __half2*)&r1.y);
        c2 = __hadd2(c2, *(const __half2*)&r1.z);
        c3 = __hadd2(c3, *(const __half2*)&r1.w);
        c0 = __hadd2(c0, *(const __half2*)&r2.x);
        c1 = __hadd2(c1, *(const __half2*)&r2.y);
        c2 = __hadd2(c2, *(const __half2*)&r2.z);
        c3 = __hadd2(c3, *(const __half2*)&r2.w);
        c0 = __hadd2(c0, *(const __half2*)&r3.x);
        c1 = __hadd2(c1, *(const __half2*)&r3.y);
        c2 = __hadd2(c2, *(const __half2*)&r3.z);
        c3 = __hadd2(c3, *(const __half2*)&r3.w);
        c0 = __hadd2(c0, *(const __half2*)&r4.x);
        c1 = __hadd2(c1, *(const __half2*)&r4.y);
        c2 = __hadd2(c2, *(const __half2*)&r4.z);
        c3 = __hadd2(c3, *(const __half2*)&r4.w);
        c0 = __hadd2(c0, *(const __half2*)&r5.x);
        c1 = __hadd2(c1, *(const __half2*)&r5.y);
        c2 = __hadd2(c2, *(const __half2*)&r5.z);
        c3 = __hadd2(c3, *(const __half2*)&r5.w);
        c0 = __hadd2(c0, *(const __half2*)&r6.x);
        c1 = __hadd2(c1, *(const __half2*)&r6.y);
        c2 = __hadd2(c2, *(const __half2*)&r6.z);
        c3 = __hadd2(c3, *(const __half2*)&r6.w);
        c0 = __hadd2(c0, *(const __half2*)&r7.x);
        c1 = __hadd2(c1, *(const __half2*)&r7.y);
        c2 = __hadd2(c2, *(const __half2*)&r7.z);
        c3 = __hadd2(c3, *(const __half2*)&r7.w);

        float2 f;
        f = __half22float2(c0); a0 += f.x; a1 += f.y;
        f = __half22float2(c1); a2 += f.x; a3 += f.y;
        f = __half22float2(c2); a4 += f.x; a5 += f.y;
        f = __half22float2(c3); a6 += f.x; a7 += f.y;
    }

    // reduce across the 4 edge subgroups (q preserved by xor 8/16)
    #pragma unroll
    for (int d = 8; d <= 16; d <<= 1) {
        a0 += __shfl_xor_sync(0xffffffffu, a0, d);
        a1 += __shfl_xor_sync(0xffffffffu, a1, d);
        a2 += __shfl_xor_sync(0xffffffffu, a2, d);
        a3 += __shfl_xor_sync(0xffffffffu, a3, d);
        a4 += __shfl_xor_sync(0xffffffffu, a4, d);
        a5 += __shfl_xor_sync(0xffffffffu, a5, d);
        a6 += __shfl_xor_sync(0xffffffffu, a6, d);
        a7 += __shfl_xor_sync(0xffffffffu, a7, d);
    }

    if (h == 0) {
        float di = rsqrtf((float)deg + 1e-7f);
        float di2 = di * di;                      // s_next = dinv^2 * sum
        __half2 o0 = __floats2half2_rn(di2 * a0, di2 * a1);
        __half2 o1 = __floats2half2_rn(di2 * a2, di2 * a3);
        __half2 o2 = __floats2half2_rn(di2 * a4, di2 * a5);
        __half2 o3 = __floats2half2_rn(di2 * a6, di2 * a7);
        uint4 o;
        o.x = *(const unsigned*)&o0; o.y = *(const unsigned*)&o1;
        o.z = *(const unsigned*)&o2; o.w = *(const unsigned*)&o3;
        y[gw * 8 + q] = o;
    }
}

// --- final: out = 0.25*(h0 + rdinv*(s1+s2+s3)); self-cleans g_cnt --------------
__global__ void k_final(const float4* __restrict__ user,
                        const float4* __restrict__ item,
                        float4* __restrict__ out, int u4, int n8) {
    int i = blockIdx.x * blockDim.x + threadIdx.x;   // uint4 index
    if (i >= n8) return;
    int f4 = i * 2;
    float4 va, vb;
    if (f4 < u4) { va = __ldg(user + f4); vb = __ldg(user + f4 + 1); }
    else         { va = __ldg(item + (f4 - u4)); vb = __ldg(item + (f4 - u4) + 1); }
    uint4 s1 = g_s[1][i], s2 = g_s[2][i], s3 = g_s[3][i];

    // read count, THEN lane (i&7)==0 zeroes it for the next graph replay.
    // 8-thread groups never straddle a warp; read precedes write in program order.
    int node = i >> 3;
    int cnt  = g_cnt[node];
    if ((i & 7) == 0) g_cnt[node] = 0;
    float rd = sqrtf((float)cnt + 1e-7f);

    float acc[8];
    #pragma unroll
    for (int k = 0; k < 4; k++) {
        float2 f1 = __half22float2(*((const __half2*)&s1 + k));
        float2 f2 = __half22float2(*((const __half2*)&s2 + k));
        float2 f3 = __half22float2(*((const __half2*)&s3 + k));
        acc[2 * k]     = f1.x + f2.x + f3.x;
        acc[2 * k + 1] = f1.y + f2.y + f3.y;
    }
    float4 oa, ob;
    oa.x = 0.25f * (va.x + rd * acc[0]);
    oa.y = 0.25f * (va.y + rd * acc[1]);
    oa.z = 0.25f * (va.z + rd * acc[2]);
    oa.w = 0.25f * (va.w + rd * acc[3]);
    ob.x = 0.25f * (vb.x + rd * acc[4]);
    ob.y = 0.25f * (vb.y + rd * acc[5]);
    ob.z = 0.25f * (vb.z + rd * acc[6]);
    ob.w = 0.25f * (vb.w + rd * acc[7]);
    out[f4]     = oa;
    out[f4 + 1] = ob;
}

extern "C" void kernel_launch(void* const* d_in, const int* in_sizes, int n_in,
                              void* d_out, int out_size) {
    const float* user = (const float*)d_in[0];
    const float* item = (const float*)d_in[1];
    const int*   rows = (const int*)  d_in[2];
    const int*   cols = (const int*)  d_in[3];
    // d_in[4] (vals) unused: reconstructed from degrees.
    float* out = (float*)d_out;

    const int U = in_sizes[0] / DIM;
    const int I = in_sizes[1] / DIM;
    const int N = U + I;
    const int NNZ = in_sizes[2];
    const int E = NNZ / 2;          // symmetric COO
    const int E4 = E / 4;

    const int n8 = N * 8;
    const int u4 = U * 16;

    void* ps;
    cudaGetSymbolAddress(&ps, g_s);
    uint4* S0 = (uint4*)ps;
    uint4* S1 = S0 + (size_t)(NMAX + 1) * 8;
    uint4* S2 = S1 + (size_t)(NMAX + 1) * 8;
    uint4* S3 = S2 + (size_t)(NMAX + 1) * 8;

    const int TB  = 256;
    const int TBG = 128;            // gather blocks
    const int gridN8  = (n8 + TB - 1) / TB;
    const int gridE4  = (E4 + TB - 1) / TB;
    const int gridW   = (N * 32 + TBG - 1) / TBG;
    const int gridPad = (N * 32 + TB - 1) / TB;

    k_permute<<<gridE4, TB>>>((const int4*)rows, (const int4*)cols, E4,
                              rows, cols, E);
    k_init_pad<<<gridN8 + gridPad, TB>>>((const float4*)user, (const float4*)item,
                                         u4, n8, N, gridN8);

    k_gather<<<gridW, TBG>>>(S0, S1, N);
    k_gather<<<gridW, TBG>>>(S1, S2, N);
    k_gather<<<gridW, TBG>>>(S2, S3, N);

    k_final<<<gridN8, TB>>>((const float4*)user, (const float4*)item,
                            (float4*)out, u4, n8);
}

// round 14
// speedup vs baseline: 1.0475x; 1.0424x over previous
#include <cuda_runtime.h>
#include <cuda_fp16.h>
#include <cstdint>

// LightGCN propagation on GB300 — round 14.
// out = (h0 + A h0 + A^2 h0 + A^3 h0)/4, A = D^-1/2 Adj D^-1/2 (COO), D=64.
//
// Structure = exact R11 (best measured: 315.5us; k_zero restored, no
// k_final self-clean — R12/R13 showed the zero-elimination bought nothing
// beyond noise). New mechanism: PDL (programmatic dependent launch) on every
// kernel after k_zero to overlap launch latency + predecessor tail waves:
//  - cudaGridDependencySynchronize() placed just before each kernel's first
//    dependent read (gathers: before pcol load; final: after h0 preload)
//  - gathers call cudaTriggerProgrammaticLaunchCompletion() right after the
//    load loop so the successor's CTAs launch during the reduce/store tail.

#define DIM    64
#define NMAX   150002
#define PAD    128          // slots per node
#define PSHIFT 7

// prescaled layer buffers s0..s3, fp16 rows of 128B (8 uint4 per row)
// +1 row per buffer: the zero sentinel at row N
__device__ uint4 g_s[4][(size_t)(NMAX + 1) * 8];
__device__ int   g_cnt[NMAX];
__device__ int   g_pcol[(size_t)NMAX * PAD];

// --- zero per-node counters + sentinel rows of all 4 s-buffers ------------------
__global__ void k_zero(int n) {
    int i = blockIdx.x * blockDim.x + threadIdx.x;
    if (i < n) g_cnt[i] = 0;
    if (i < 32) {   // 4 buffers x 8 uint4 sentinel row
        g_s[i >> 3][(size_t)n * 8 + (i & 7)] = make_uint4(0u, 0u, 0u, 0u);
    }
}

// --- permute into padded slots: 4 symmetric edge-pairs per thread ---------------
__global__ void k_permute(const int4* __restrict__ rows4,
                          const int4* __restrict__ cols4, int E4,
                          const int* __restrict__ rows,
                          const int* __restrict__ cols, int E) {
    int i = blockIdx.x * blockDim.x + threadIdx.x;
    // g_cnt is written by the immediate predecessor (k_zero): sync first.
    cudaGridDependencySynchronize();
    if (i < E4) {
        int4 r = __ldg(rows4 + i);
        int4 c = __ldg(cols4 + i);
        int p;
        p = atomicAdd(&g_cnt[r.x], 1); g_pcol[(r.x << PSHIFT) + p] = c.x;
        p = atomicAdd(&g_cnt[c.x], 1); g_pcol[(c.x << PSHIFT) + p] = r.x;
        p = atomicAdd(&g_cnt[r.y], 1); g_pcol[(r.y << PSHIFT) + p] = c.y;
        p = atomicAdd(&g_cnt[c.y], 1); g_pcol[(c.y << PSHIFT) + p] = r.y;
        p = atomicAdd(&g_cnt[r.z], 1); g_pcol[(r.z << PSHIFT) + p] = c.z;
        p = atomicAdd(&g_cnt[c.z], 1); g_pcol[(c.z << PSHIFT) + p] = r.z;
        p = atomicAdd(&g_cnt[r.w], 1); g_pcol[(r.w << PSHIFT) + p] = c.w;
        p = atomicAdd(&g_cnt[c.w], 1); g_pcol[(c.w << PSHIFT) + p] = r.w;
    }
    int t = E4 * 4 + i;
    if (i < E - E4 * 4) {
        int r = __ldg(rows + t), c = __ldg(cols + t);
        int p;
        p = atomicAdd(&g_cnt[r], 1); g_pcol[(r << PSHIFT) + p] = c;
        p = atomicAdd(&g_cnt[c], 1); g_pcol[(c << PSHIFT) + p] = r;
    }
}

// --- fused init + sentinel pad -----------------------------------------------
__global__ void k_init_pad(const float4* __restrict__ user,
                           const float4* __restrict__ item,
                           int u4, int n8, int n, int initBlocks) {
    if ((int)blockIdx.x < initBlocks) {
        int i = blockIdx.x * blockDim.x + threadIdx.x;   // uint4 index
        if (i >= n8) return;
        int f4 = i * 2;
        // h0 loads are pure inputs: overlap with permute's tail.
        float4 va, vb;
        if (f4 < u4) { va = __ldg(user + f4); vb = __ldg(user + f4 + 1); }
        else         { va = __ldg(item + (f4 - u4)); vb = __ldg(item + (f4 - u4) + 1); }
        cudaGridDependencySynchronize();                  // g_cnt from permute
        float di = rsqrtf((float)__ldg(&g_cnt[i >> 3]) + 1e-7f);
        __half2 h0 = __floats2half2_rn(di * va.x, di * va.y);
        __half2 h1 = __floats2half2_rn(di * va.z, di * va.w);
        __half2 h2 = __floats2half2_rn(di * vb.x, di * vb.y);
        __half2 h3 = __floats2half2_rn(di * vb.z, di * vb.w);
        uint4 o;
        o.x = *(const unsigned*)&h0; o.y = *(const unsigned*)&h1;
        o.z = *(const unsigned*)&h2; o.w = *(const unsigned*)&h3;
        g_s[0][i] = o;
    } else {
        int j = ((int)blockIdx.x - initBlocks) * blockDim.x + threadIdx.x;
        if (j >= n * 32) return;
        cudaGridDependencySynchronize();                  // g_cnt from permute
        int node = j >> 5;
        int k    = j & 31;
        int deg  = __ldg(&g_cnt[node]);
        int slot = (deg & ~31) + k;     // last (partial) chunk of the bucket
        if (slot >= deg && slot < PAD)
            g_pcol[(node << PSHIFT) + slot] = n;   // sentinel: zero row
    }
}

// --- gather SpMM: warp/row; unconditional batched MLP-8 chunks; HADD2 ----------
// R11 body + PDL: sync before pcol (init_pad writes sentinel slots),
// trigger right after the load loop.
__global__ void k_gather(const uint4* __restrict__ x,
                         uint4* __restrict__ y, int n) {
    int gw   = (blockIdx.x * blockDim.x + threadIdx.x) >> 5;
    int lane = threadIdx.x & 31;
    if (gw >= n) return;
    int s   = gw << PSHIFT;
    int deg = __ldg(&g_cnt[gw]);   // written >=2 kernels back: transitively done
    int e   = s + deg;
    int h = lane >> 3;          // edge-of-4 subgroup (0..3)
    int q = lane & 7;           // 16B slice of the 128B row

    float a0 = 0.f, a1 = 0.f, a2 = 0.f, a3 = 0.f;
    float a4 = 0.f, a5 = 0.f, a6 = 0.f, a7 = 0.f;

    cudaGridDependencySynchronize();            // pcol pad / x from predecessor

    int c = __ldg(&g_pcol[s + lane]);           // always in-bounds

    for (int base = s; base < e; base += 32) {
        int c_cur = c;
        if (base + 32 < e)                       // prefetch next chunk's indices
            c = __ldg(&g_pcol[base + 32 + lane]);

        // 8 uniform group indices (slots past deg hold the zero sentinel)
        int cj0 = __shfl_sync(0xffffffffu, c_cur,  0 + h);
        int cj1 = __shfl_sync(0xffffffffu, c_cur,  4 + h);
        int cj2 = __shfl_sync(0xffffffffu, c_cur,  8 + h);
        int cj3 = __shfl_sync(0xffffffffu, c_cur, 12 + h);
        int cj4 = __shfl_sync(0xffffffffu, c_cur, 16 + h);
        int cj5 = __shfl_sync(0xffffffffu, c_cur, 20 + h);
        int cj6 = __shfl_sync(0xffffffffu, c_cur, 24 + h);
        int cj7 = __shfl_sync(0xffffffffu, c_cur, 28 + h);

        // 8 unconditional back-to-back LDG.128 (MLP 8)
        uint4 r0 = __ldg(x + cj0 * 8 + q);
        uint4 r1 = __ldg(x + cj1 * 8 + q);
        uint4 r2 = __ldg(x + cj2 * 8 + q);
        uint4 r3 = __ldg(x + cj3 * 8 + q);
        uint4 r4 = __ldg(x + cj4 * 8 + q);
        uint4 r5 = __ldg(x + cj5 * 8 + q);
        uint4 r6 = __ldg(x + cj6 * 8 + q);
        uint4 r7 = __ldg(x + cj7 * 8 + q);

        // fp16 chunk accumulation (sentinel zeros are exact)
        __half2 zz = __floats2half2_rn(0.f, 0.f);
        __half2 c0 = zz, c1 = zz, c2 = zz, c3 = zz;
        c0 = __hadd2(c0, *(const __half2*)&r0.x);
        c1 = __hadd2(c1, *(const __half2*)&r0.y);
        c2 = __hadd2(c2, *(const __half2*)&r0.z);
        c3 = __hadd2(c3, *(const __half2*)&r0.w);
        c0 = __hadd2(c0, *(const __half2*)&r1.x);
        c1 = __hadd2(c1, *(const __half2*)&r1.y);
        c2 = __hadd2(c2, *(const __half2*)&r1.z);
        c3 = __hadd2(c3, *(const __half2*)&r1.w);
        c0 = __hadd2(c0, *(const __half2*)&r2.x);
        c1 = __hadd2(c1, *(const __half2*)&r2.y);
        c2 = __hadd2(c2, *(const __half2*)&r2.z);
        c3 = __hadd2(c3, *(const __half2*)&r2.w);
        c0 = __hadd2(c0, *(const __half2*)&r3.x);
        c1 = __hadd2(c1, *(const __half2*)&r3.y);
        c2 = __hadd2(c2, *(const __half2*)&r3.z);
        c3 = __hadd2(c3, *(const __half2*)&r3.w);
        c0 = __hadd2(c0, *(const __half2*)&r4.x);
        c1 = __hadd2(c1, *(const __half2*)&r4.y);
        c2 = __hadd2(c2, *(const __half2*)&r4.z);
        c3 = __hadd2(c3, *(const __half2*)&r4.w);
        c0 = __hadd2(c0, *(const __half2*)&r5.x);
        c1 = __hadd2(c1, *(const __half2*)&r5.y);
        c2 = __hadd2(c2, *(const __half2*)&r5.z);
        c3 = __hadd2(c3, *(const __half2*)&r5.w);
        c0 = __hadd2(c0, *(const __half2*)&r6.x);
        c1 = __hadd2(c1, *(const __half2*)&r6.y);
        c2 = __hadd2(c2, *(const __half2*)&r6.z);
        c3 = __hadd2(c3, *(const __half2*)&r6.w);
        c0 = __hadd2(c0, *(const __half2*)&r7.x);
        c1 = __hadd2(c1, *(const __half2*)&r7.y);
        c2 = __hadd2(c2, *(const __half2*)&r7.z);
        c3 = __hadd2(c3, *(const __half2*)&r7.w);

        float2 f;
        f = __half22float2(c0); a0 += f.x; a1 += f.y;
        f = __half22float2(c1); a2 += f.x; a3 += f.y;
        f = __half22float2(c2); a4 += f.x; a5 += f.y;
        f = __half22float2(c3); a6 += f.x; a7 += f.y;
    }

    // loads done: let the successor kernel's CTAs start launching
    cudaTriggerProgrammaticLaunchCompletion();

    // reduce across the 4 edge subgroups (q preserved by xor 8/16)
    #pragma unroll
    for (int d = 8; d <= 16; d <<= 1) {
        a0 += __shfl_xor_sync(0xffffffffu, a0, d);
        a1 += __shfl_xor_sync(0xffffffffu, a1, d);
        a2 += __shfl_xor_sync(0xffffffffu, a2, d);
        a3 += __shfl_xor_sync(0xffffffffu, a3, d);
        a4 += __shfl_xor_sync(0xffffffffu, a4, d);
        a5 += __shfl_xor_sync(0xffffffffu, a5, d);
        a6 += __shfl_xor_sync(0xffffffffu, a6, d);
        a7 += __shfl_xor_sync(0xffffffffu, a7, d);
    }

    if (h == 0) {
        float di = rsqrtf((float)deg + 1e-7f);
        float di2 = di * di;                      // s_next = dinv^2 * sum
        __half2 o0 = __floats2half2_rn(di2 * a0, di2 * a1);
        __half2 o1 = __floats2half2_rn(di2 * a2, di2 * a3);
        __half2 o2 = __floats2half2_rn(di2 * a4, di2 * a5);
        __half2 o3 = __floats2half2_rn(di2 * a6, di2 * a7);
        uint4 o;
        o.x = *(const unsigned*)&o0; o.y = *(const unsigned*)&o1;
        o.z = *(const unsigned*)&o2; o.w = *(const unsigned*)&o3;
        y[gw * 8 + q] = o;
    }
}

// --- final: out = 0.25*(h0 + rdinv*(s1+s2+s3)), fp32 ---------------------------
// PDL: h0 + cnt loads are independent of gather3 -> preload before the sync.
__global__ void k_final(const float4* __restrict__ user,
                        const float4* __restrict__ item,
                        float4* __restrict__ out, int u4, int n8) {
    int i = blockIdx.x * blockDim.x + threadIdx.x;   // uint4 index
    if (i >= n8) return;
    int f4 = i * 2;
    float4 va, vb;
    if (f4 < u4) { va = __ldg(user + f4); vb = __ldg(user + f4 + 1); }
    else         { va = __ldg(item + (f4 - u4)); vb = __ldg(item + (f4 - u4) + 1); }
    float rd = sqrtf((float)__ldg(&g_cnt[i >> 3]) + 1e-7f);

    cudaGridDependencySynchronize();     // s1..s3 from the gathers

    uint4 s1 = g_s[1][i], s2 = g_s[2][i], s3 = g_s[3][i];

    float acc[8];
    #pragma unroll
    for (int k = 0; k < 4; k++) {
        float2 f1 = __half22float2(*((const __half2*)&s1 + k));
        float2 f2 = __half22float2(*((const __half2*)&s2 + k));
        float2 f3 = __half22float2(*((const __half2*)&s3 + k));
        acc[2 * k]     = f1.x + f2.x + f3.x;
        acc[2 * k + 1] = f1.y + f2.y + f3.y;
    }
    float4 oa, ob;
    oa.x = 0.25f * (va.x + rd * acc[0]);
    oa.y = 0.25f * (va.y + rd * acc[1]);
    oa.z = 0.25f * (va.z + rd * acc[2]);
    oa.w = 0.25f * (va.w + rd * acc[3]);
    ob.x = 0.25f * (vb.x + rd * acc[4]);
    ob.y = 0.25f * (vb.y + rd * acc[5]);
    ob.z = 0.25f * (vb.z + rd * acc[6]);
    ob.w = 0.25f * (vb.w + rd * acc[7]);
    out[f4]     = oa;
    out[f4 + 1] = ob;
}

// host helper: launch with ProgrammaticStreamSerialization
template <typename... Args>
static void launch_pdl(void (*kern)(Args...), int grid, int block, Args... args) {
    cudaLaunchAttribute attr[1];
    attr[0].id = cudaLaunchAttributeProgrammaticStreamSerialization;
    attr[0].val.programmaticStreamSerializationAllowed = 1;
    cudaLaunchConfig_t cfg{};
    cfg.gridDim  = dim3((unsigned)grid, 1, 1);
    cfg.blockDim = dim3((unsigned)block, 1, 1);
    cfg.dynamicSmemBytes = 0;
    cfg.stream = 0;
    cfg.attrs = attr;
    cfg.numAttrs = 1;
    cudaLaunchKernelEx(&cfg, kern, args...);
}

extern "C" void kernel_launch(void* const* d_in, const int* in_sizes, int n_in,
                              void* d_out, int out_size) {
    const float* user = (const float*)d_in[0];
    const float* item = (const float*)d_in[1];
    const int*   rows = (const int*)  d_in[2];
    const int*   cols = (const int*)  d_in[3];
    // d_in[4] (vals) unused: reconstructed from degrees.
    float* out = (float*)d_out;

    const int U = in_sizes[0] / DIM;
    const int I = in_sizes[1] / DIM;
    const int N = U + I;
    const int NNZ = in_sizes[2];
    const int E = NNZ / 2;          // symmetric COO
    const int E4 = E / 4;

    const int n8 = N * 8;
    const int u4 = U * 16;

    void* ps;
    cudaGetSymbolAddress(&ps, g_s);
    uint4* S0 = (uint4*)ps;
    uint4* S1 = S0 + (size_t)(NMAX + 1) * 8;
    uint4* S2 = S1 + (size_t)(NMAX + 1) * 8;
    uint4* S3 = S2 + (size_t)(NMAX + 1) * 8;

    const int TB  = 256;
    const int TBG = 128;            // gather blocks
    const int gridN   = (N + TB - 1) / TB;
    const int gridN8  = (n8 + TB - 1) / TB;
    const int gridE4  = (E4 + TB - 1) / TB;
    const int gridW   = (N * 32 + TBG - 1) / TBG;
    const int gridPad = (N * 32 + TB - 1) / TB;

    k_zero<<<gridN, TB>>>(N);

    launch_pdl(k_permute, gridE4, TB,
               (const int4*)rows, (const int4*)cols, E4, rows, cols, E);
    launch_pdl(k_init_pad, gridN8 + gridPad, TB,
               (const float4*)user, (const float4*)item, u4, n8, N, gridN8);

    launch_pdl(k_gather, gridW, TBG, (const uint4*)S0, S1, N);
    launch_pdl(k_gather, gridW, TBG, (const uint4*)S1, S2, N);
    launch_pdl(k_gather, gridW, TBG, (const uint4*)S2, S3, N);

    launch_pdl(k_final, gridN8, TB,
               (const float4*)user, (const float4*)item, (float4*)out, u4, n8);
}